// round 4
// baseline (speedup 1.0000x reference)
#include <cuda_runtime.h>
#include <cuda_bf16.h>
#include <cstdint>

// ============================================================================
// SimpleBNN on GB300 — sm_103 (non-'a' target: NO tcgen05, use mma.sync)
//   h1 = sign(x) @ sign(w1)^T + b1 ; a1 = sign(h1)
//   h2 = a1      @ sign(w2)^T + b2 ; a2 = sign(h2)
//   out = a2 @ w3^T + b3
// Layers 1/2: s8 IMMA (exact ternary math, s32 accum exact).
// Layer 3:    bf16 HMMA with w3 = hi+lo bf16 split folded into K=8192.
// ============================================================================

#define DINL __device__ __forceinline__

// ---------------- device scratch ----------------
__device__ __align__(16) int8_t   g_X8[(size_t)8192 * 4096];  // sign(x)       s8
__device__ __align__(16) int8_t   g_W1 [(size_t)4096 * 4096]; // sign(w1)      s8
__device__ __align__(16) int8_t   g_W2 [(size_t)4096 * 4096]; // sign(w2)      s8
__device__ __align__(16) int8_t   g_A1 [(size_t)8192 * 4096]; // a1 = sign(h1) s8
__device__ __align__(16) uint16_t g_A2 [(size_t)8192 * 4096]; // a2 = sign(h2) bf16
__device__ __align__(16) uint8_t  g_B3 [(size_t)1024 * 16384];// w3 rows: [hi(8192B) | lo(8192B)]

// ---------------- helpers ----------------
DINL uint32_t smem_u32(const void* p) {
    uint32_t a;
    asm("{ .reg .u64 t; cvta.to.shared.u64 t, %1; cvt.u32.u64 %0, t; }" : "=r"(a) : "l"(p));
    return a;
}

DINL uint32_t s8byte(float v) {           // sign -> s8 byte: +1 -> 1, -1 -> 0xFF, 0 -> 0
    uint32_t u = __float_as_uint(v);
    return ((u << 1) == 0u) ? 0u : ((u >> 31) ? 0xFFu : 0x01u);
}
DINL uint32_t bf16sgn(float v) {          // sign -> bf16 bits: +-1.0f or 0
    uint32_t u = __float_as_uint(v);
    return ((u << 1) == 0u) ? 0u : (0x3F80u | ((u >> 31) << 15));
}

#define CP_ASYNC16(dst, src) \
    asm volatile("cp.async.cg.shared.global [%0], [%1], 16;" :: "r"(dst), "l"(src))
#define CP_COMMIT()  asm volatile("cp.async.commit_group;" ::: "memory")
#define CP_WAIT2()   asm volatile("cp.async.wait_group 2;" ::: "memory")

#define LDSM_X4(r, addr)                                                      \
    asm volatile("ldmatrix.sync.aligned.m8n8.x4.shared.b16 {%0,%1,%2,%3}, [%4];" \
        : "=r"((r)[0]), "=r"((r)[1]), "=r"((r)[2]), "=r"((r)[3]) : "r"(addr))

DINL void mma_s8(uint32_t c[4], const uint32_t a[4], uint32_t b0, uint32_t b1) {
    asm volatile(
        "mma.sync.aligned.m16n8k32.row.col.s32.s8.s8.s32 "
        "{%0,%1,%2,%3}, {%4,%5,%6,%7}, {%8,%9}, {%0,%1,%2,%3};"
        : "+r"(c[0]), "+r"(c[1]), "+r"(c[2]), "+r"(c[3])
        : "r"(a[0]), "r"(a[1]), "r"(a[2]), "r"(a[3]), "r"(b0), "r"(b1));
}
DINL void mma_bf16(float c[4], const uint32_t a[4], uint32_t b0, uint32_t b1) {
    asm volatile(
        "mma.sync.aligned.m16n8k16.row.col.f32.bf16.bf16.f32 "
        "{%0,%1,%2,%3}, {%4,%5,%6,%7}, {%8,%9}, {%0,%1,%2,%3};"
        : "+f"(c[0]), "+f"(c[1]), "+f"(c[2]), "+f"(c[3])
        : "r"(a[0]), "r"(a[1]), "r"(a[2]), "r"(a[3]), "r"(b0), "r"(b1));
}

// ============================================================================
// Prep kernels
// ============================================================================
template <int SEL>
__global__ void prep_s8(const float* __restrict__ src) {
    int8_t* dst = (SEL == 0) ? g_X8 : (SEL == 1) ? g_W1 : g_W2;
    size_t t = (size_t)blockIdx.x * 256 + threadIdx.x;     // exact grid, no bounds check
    const float4* s = (const float4*)src + t * 4;
    float4 f0 = s[0], f1 = s[1], f2 = s[2], f3 = s[3];
    uint4 o;
    o.x = s8byte(f0.x) | (s8byte(f0.y) << 8) | (s8byte(f0.z) << 16) | (s8byte(f0.w) << 24);
    o.y = s8byte(f1.x) | (s8byte(f1.y) << 8) | (s8byte(f1.z) << 16) | (s8byte(f1.w) << 24);
    o.z = s8byte(f2.x) | (s8byte(f2.y) << 8) | (s8byte(f2.z) << 16) | (s8byte(f2.w) << 24);
    o.w = s8byte(f3.x) | (s8byte(f3.y) << 8) | (s8byte(f3.z) << 16) | (s8byte(f3.w) << 24);
    *(uint4*)(dst + t * 16) = o;
}

// w3 [1000,4096] f32 -> g_B3 rows n (0..1023): bytes [0,8192)=hi bf16, [8192,16384)=lo bf16
__global__ void prep_w3k(const float* __restrict__ w3) {
    size_t t = (size_t)blockIdx.x * 256 + threadIdx.x;     // 524288 threads exact
    int k8 = (int)(t & 511) * 8;
    int n  = (int)(t >> 9);
    float f[8];
    if (n < 1000) {
        const float4* s = (const float4*)(w3 + (size_t)n * 4096 + k8);
        float4 a = s[0], b = s[1];
        f[0] = a.x; f[1] = a.y; f[2] = a.z; f[3] = a.w;
        f[4] = b.x; f[5] = b.y; f[6] = b.z; f[7] = b.w;
    } else {
        #pragma unroll
        for (int i = 0; i < 8; i++) f[i] = 0.0f;
    }
    uint32_t hw[8], lw[8];
    #pragma unroll
    for (int i = 0; i < 8; i++) {
        __nv_bfloat16 h = __float2bfloat16(f[i]);
        float res = f[i] - __bfloat162float(h);
        __nv_bfloat16 l = __float2bfloat16(res);
        hw[i] = (uint32_t)__bfloat16_as_ushort(h);
        lw[i] = (uint32_t)__bfloat16_as_ushort(l);
    }
    uint4 oh, ol;
    oh.x = hw[0] | (hw[1] << 16); oh.y = hw[2] | (hw[3] << 16);
    oh.z = hw[4] | (hw[5] << 16); oh.w = hw[6] | (hw[7] << 16);
    ol.x = lw[0] | (lw[1] << 16); ol.y = lw[2] | (lw[3] << 16);
    ol.z = lw[4] | (lw[5] << 16); ol.w = lw[6] | (lw[7] << 16);
    uint8_t* row = g_B3 + (size_t)n * 16384;
    *(uint4*)(row + (size_t)k8 * 2)        = oh;
    *(uint4*)(row + 8192 + (size_t)k8 * 2) = ol;
}

// ============================================================================
// Unified GEMM: CTA 128x128, 8 warps (warp tile 32x64), K-chunk 64 B / stage,
// 4-stage cp.async pipeline, SMEM stride 80 B (conflict-free, 16B-aligned).
// MODE 0: s8 IMMA,  A=g_X8, B=g_W1, out = sign(+b1) -> g_A1 (s8)
// MODE 1: s8 IMMA,  A=g_A1, B=g_W2, out = sign(+b2) -> g_A2 (bf16)
// MODE 2: bf16 HMMA, A=g_A2 (wrap k mod 4096), B=g_B3 (K=8192: hi|lo),
//         out = acc + b3 -> float [8192,1000]
// ============================================================================
static const int SSTRIDE   = 80;           // smem row stride (bytes)
static const int STAGE_B   = 128 * SSTRIDE;           // 10240 per operand
static const int STAGE_TOT = 2 * STAGE_B;             // 20480
static const int NSTAGE    = 4;
static const int SMEM_BYTES = NSTAGE * STAGE_TOT + 512;  // + bias

template <int MODE>
__global__ void __launch_bounds__(256, 1) gemm_k(const float* __restrict__ bias,
                                                 float* __restrict__ outf) {
    constexpr int KCH   = (MODE == 2) ? 256 : 64;      // 64-byte k-chunks
    constexpr int ARB   = (MODE == 2) ? 8192 : 4096;   // A row bytes
    constexpr int AMASK = ARB - 1;
    constexpr int BRB   = (MODE == 2) ? 16384 : 4096;  // B row bytes

    const uint8_t* Ag = (MODE == 0) ? (const uint8_t*)g_X8
                      : (MODE == 1) ? (const uint8_t*)g_A1
                                    : (const uint8_t*)g_A2;
    const uint8_t* Bg = (MODE == 0) ? (const uint8_t*)g_W1
                      : (MODE == 1) ? (const uint8_t*)g_W2
                                    : (const uint8_t*)g_B3;

    extern __shared__ __align__(16) uint8_t smem[];
    const int tid  = threadIdx.x;
    const int lane = tid & 31;
    const int wid  = tid >> 5;
    const int mt = blockIdx.x, nt = blockIdx.y;
    const int m_w = (wid >> 1) * 32;      // warp M offset in CTA tile
    const int n_w = (wid & 1) * 64;       // warp N offset
    const uint32_t sbase = smem_u32(smem);
    float* s_bias = (float*)(smem + NSTAGE * STAGE_TOT);

    if (tid < 128) {
        int n = nt * 128 + tid;
        s_bias[tid] = (MODE == 2) ? ((n < 1000) ? bias[n] : 0.0f) : bias[n];
    }

    const uint8_t* Abase = Ag + (size_t)mt * 128 * ARB;
    const uint8_t* Bbase = Bg + (size_t)nt * 128 * BRB;

    auto load_stage = [&](int st, int kb) {
        uint32_t sA = sbase + st * STAGE_TOT;
        uint32_t sB = sA + STAGE_B;
        #pragma unroll
        for (int i = 0; i < 2; i++) {
            int c  = tid + 256 * i;           // 512 chunks of 16B per operand
            int r  = c >> 2;
            int cb = (c & 3) * 16;
            const uint8_t* asrc = Abase + (size_t)r * ARB + (uint32_t)((kb + cb) & AMASK);
            CP_ASYNC16(sA + (uint32_t)(r * SSTRIDE + cb), asrc);
            const uint8_t* bsrc = Bbase + (size_t)r * BRB + (uint32_t)(kb + cb);
            CP_ASYNC16(sB + (uint32_t)(r * SSTRIDE + cb), bsrc);
        }
    };

    uint32_t ci[2][8][4];
    float    cf[2][8][4];
    if constexpr (MODE < 2) {
        #pragma unroll
        for (int a = 0; a < 2; a++)
            #pragma unroll
            for (int b = 0; b < 8; b++)
                #pragma unroll
                for (int c = 0; c < 4; c++) ci[a][b][c] = 0u;
    } else {
        #pragma unroll
        for (int a = 0; a < 2; a++)
            #pragma unroll
            for (int b = 0; b < 8; b++)
                #pragma unroll
                for (int c = 0; c < 4; c++) cf[a][b][c] = 0.0f;
    }

    // prologue: stages 0..2
    #pragma unroll
    for (int s = 0; s < 3; s++) { load_stage(s, s * 64); CP_COMMIT(); }

    #pragma unroll 1
    for (int ks = 0; ks < KCH; ks++) {
        CP_WAIT2();
        __syncthreads();
        if (ks + 3 < KCH) load_stage((ks + 3) & 3, (ks + 3) * 64);
        CP_COMMIT();

        const uint32_t sA = sbase + (ks & 3) * STAGE_TOT;
        const uint32_t sB = sA + STAGE_B;

        uint32_t af[2][2][4];    // [mi][j] : one ldmatrix.x4 each
        uint32_t bf_[8][4];      // [ni]    : r0,r1 = j0 b0,b1 ; r2,r3 = j1 b0,b1
        #pragma unroll
        for (int mi = 0; mi < 2; mi++)
            #pragma unroll
            for (int j = 0; j < 2; j++) {
                uint32_t row = (uint32_t)(m_w + mi * 16 + ((lane >> 3) & 1) * 8 + (lane & 7));
                uint32_t addr = sA + row * SSTRIDE + (uint32_t)(j * 32 + (lane >> 4) * 16);
                LDSM_X4(af[mi][j], addr);
            }
        #pragma unroll
        for (int ni = 0; ni < 8; ni++) {
            uint32_t row = (uint32_t)(n_w + ni * 8 + (lane & 7));
            uint32_t addr = sB + row * SSTRIDE + (uint32_t)((lane >> 3) * 16);
            LDSM_X4(bf_[ni], addr);
        }

        #pragma unroll
        for (int j = 0; j < 2; j++)
            #pragma unroll
            for (int mi = 0; mi < 2; mi++)
                #pragma unroll
                for (int ni = 0; ni < 8; ni++) {
                    if constexpr (MODE < 2)
                        mma_s8(ci[mi][ni], af[mi][j], bf_[ni][2 * j], bf_[ni][2 * j + 1]);
                    else
                        mma_bf16(cf[mi][ni], af[mi][j], bf_[ni][2 * j], bf_[ni][2 * j + 1]);
                }
    }

    // ---------------- epilogue ----------------
    const int g = lane >> 2, t4 = lane & 3;
    #pragma unroll
    for (int mi = 0; mi < 2; mi++) {
        const int r0 = mt * 128 + m_w + mi * 16 + g;
        #pragma unroll
        for (int ni = 0; ni < 8; ni++) {
            const int nl = n_w + ni * 8 + t4 * 2;
            const int ng = nt * 128 + nl;
            const float b0 = s_bias[nl], b1 = s_bias[nl + 1];
            if constexpr (MODE == 0) {
                float f0 = (float)(int)ci[mi][ni][0] + b0;
                float f1 = (float)(int)ci[mi][ni][1] + b1;
                float f2 = (float)(int)ci[mi][ni][2] + b0;
                float f3 = (float)(int)ci[mi][ni][3] + b1;
                uint16_t p0 = (uint16_t)(s8byte(f0) | (s8byte(f1) << 8));
                uint16_t p1 = (uint16_t)(s8byte(f2) | (s8byte(f3) << 8));
                *(uint16_t*)((uint8_t*)g_A1 + (size_t)r0 * 4096 + ng)       = p0;
                *(uint16_t*)((uint8_t*)g_A1 + (size_t)(r0 + 8) * 4096 + ng) = p1;
            } else if constexpr (MODE == 1) {
                float f0 = (float)(int)ci[mi][ni][0] + b0;
                float f1 = (float)(int)ci[mi][ni][1] + b1;
                float f2 = (float)(int)ci[mi][ni][2] + b0;
                float f3 = (float)(int)ci[mi][ni][3] + b1;
                uint32_t p0 = bf16sgn(f0) | (bf16sgn(f1) << 16);
                uint32_t p1 = bf16sgn(f2) | (bf16sgn(f3) << 16);
                *(uint32_t*)&g_A2[(size_t)r0 * 4096 + ng]       = p0;
                *(uint32_t*)&g_A2[(size_t)(r0 + 8) * 4096 + ng] = p1;
            } else {
                float f0 = cf[mi][ni][0] + b0;
                float f1 = cf[mi][ni][1] + b1;
                float f2 = cf[mi][ni][2] + b0;
                float f3 = cf[mi][ni][3] + b1;
                if (ng < 1000) {
                    outf[(size_t)r0 * 1000 + ng]       = f0;
                    outf[(size_t)(r0 + 8) * 1000 + ng] = f2;
                }
                if (ng + 1 < 1000) {
                    outf[(size_t)r0 * 1000 + ng + 1]       = f1;
                    outf[(size_t)(r0 + 8) * 1000 + ng + 1] = f3;
                }
            }
        }
    }
}

// ============================================================================
// kernel_launch
// ============================================================================
extern "C" void kernel_launch(void* const* d_in, const int* in_sizes, int n_in,
                              void* d_out, int out_size) {
    (void)in_sizes; (void)n_in; (void)out_size;
    const float* x  = (const float*)d_in[0];
    const float* w1 = (const float*)d_in[1];
    const float* b1 = (const float*)d_in[2];
    const float* w2 = (const float*)d_in[3];
    const float* b2 = (const float*)d_in[4];
    const float* w3 = (const float*)d_in[5];
    const float* b3 = (const float*)d_in[6];
    float* out = (float*)d_out;

    cudaFuncSetAttribute(gemm_k<0>, cudaFuncAttributeMaxDynamicSharedMemorySize, SMEM_BYTES);
    cudaFuncSetAttribute(gemm_k<1>, cudaFuncAttributeMaxDynamicSharedMemorySize, SMEM_BYTES);
    cudaFuncSetAttribute(gemm_k<2>, cudaFuncAttributeMaxDynamicSharedMemorySize, SMEM_BYTES);

    prep_s8<0><<<8192, 256>>>(x);    // 8192*4096 / 16
    prep_s8<1><<<4096, 256>>>(w1);   // 4096*4096 / 16
    prep_s8<2><<<4096, 256>>>(w2);
    prep_w3k<<<2048, 256>>>(w3);     // 1024*512

    gemm_k<0><<<dim3(64, 32), 256, SMEM_BYTES>>>(b1, nullptr);
    gemm_k<1><<<dim3(64, 32), 256, SMEM_BYTES>>>(b2, nullptr);
    gemm_k<2><<<dim3(64, 8),  256, SMEM_BYTES>>>(b3, out);
}

// round 5
// speedup vs baseline: 1.0764x; 1.0764x over previous
#include <cuda_runtime.h>
#include <cuda_bf16.h>
#include <cstdint>

// ============================================================================
// SimpleBNN on GB300 — sm_103 (non-'a': no tcgen05; mma.sync + cp.async.bulk)
//   h1 = sign(x) @ sign(w1)^T + b1 ; a1 = sign(h1)
//   h2 = a1      @ sign(w2)^T + b2 ; a2 = sign(h2)
//   out = a2 @ w3^T + b3
// Layers 1/2: s8 IMMA (exact ternary, s32 accum exact).
// Layer 3:    bf16 HMMA, w3 = hi+lo bf16 split folded into K=8192 (err ~1e-5).
// Mainloop: 2x cp.async.bulk per stage (16KB A + 32KB B, pre-swizzled in GMEM)
// + 4-stage mbarrier pipeline. CTA tile 128x256, 8 warps, warp tile 64x64.
// ============================================================================

#define DINL __device__ __forceinline__

// ---------------- device scratch ----------------
// A-layout  : 16KB blocks (mrow-tile, kstage): 128 rows x 128B, SW128-swizzled
// B-layout  : 32KB blocks (ncol-tile, kstage): 256 rows x 128B, SW128-swizzled
__device__ __align__(128) uint8_t g_A1[(size_t)64 * 32 * 16384];   // sign(x)  s8   32MB
__device__ __align__(128) uint8_t g_W1[(size_t)16 * 32 * 32768];   // sign(w1) s8   16MB
__device__ __align__(128) uint8_t g_W2[(size_t)16 * 32 * 32768];   // sign(w2) s8   16MB
__device__ __align__(128) uint8_t g_A2[(size_t)64 * 32 * 16384];   // a1       s8   32MB
__device__ __align__(128) uint8_t g_A3[(size_t)64 * 64 * 16384];   // a2       bf16 64MB
__device__ __align__(128) uint8_t g_B3[(size_t)4 * 128 * 32768];   // w3 hi|lo bf16 16MB

// ---------------- helpers ----------------
DINL uint32_t smem_u32(const void* p) {
    uint32_t a;
    asm("{ .reg .u64 t; cvta.to.shared.u64 t, %1; cvt.u32.u64 %0, t; }" : "=r"(a) : "l"(p));
    return a;
}
DINL uint32_t s8byte(float v) {     // sign -> s8: +1 -> 1, -1 -> 0xFF, 0 -> 0
    uint32_t u = __float_as_uint(v);
    return ((u << 1) == 0u) ? 0u : ((u >> 31) ? 0xFFu : 0x01u);
}
DINL uint32_t bf16sgn(float v) {    // sign -> bf16 bits
    uint32_t u = __float_as_uint(v);
    return ((u << 1) == 0u) ? 0u : (0x3F80u | ((u >> 31) << 15));
}
DINL uint32_t pack4s8(float a, float b, float c, float d) {
    return s8byte(a) | (s8byte(b) << 8) | (s8byte(c) << 16) | (s8byte(d) << 24);
}

#define MBAR_INIT(addr, cnt) \
    asm volatile("mbarrier.init.shared.b64 [%0], %1;" :: "r"(addr), "r"(cnt) : "memory")
#define MBAR_EXPECT_TX(addr, tx) \
    asm volatile("mbarrier.arrive.expect_tx.shared.b64 _, [%0], %1;" \
                 :: "r"(addr), "r"(tx) : "memory")
#define MBAR_WAIT(addr, parity) do {                                          \
    asm volatile("{\n\t.reg .pred P1;\n\t"                                    \
        "WAIT_%=:\n\t"                                                        \
        "mbarrier.try_wait.parity.acquire.cta.shared::cta.b64 P1, [%0], %1, 0x989680;\n\t" \
        "@P1 bra.uni DONE_%=;\n\t"                                            \
        "bra.uni WAIT_%=;\n\t"                                                \
        "DONE_%=:\n\t}"                                                       \
        :: "r"((uint32_t)(addr)), "r"((uint32_t)(parity)) : "memory");        \
} while (0)
#define BULK_G2S(dst, src, bytes, mbar)                                       \
    asm volatile("cp.async.bulk.shared::cluster.global.mbarrier::complete_tx::bytes " \
                 "[%0], [%1], %2, [%3];"                                      \
                 :: "r"((uint32_t)(dst)), "l"(src), "r"((uint32_t)(bytes)),   \
                    "r"((uint32_t)(mbar)) : "memory")

#define LDSM_X4(r, addr)                                                      \
    asm volatile("ldmatrix.sync.aligned.m8n8.x4.shared.b16 {%0,%1,%2,%3}, [%4];" \
        : "=r"((r)[0]), "=r"((r)[1]), "=r"((r)[2]), "=r"((r)[3]) : "r"(addr))
#define LDSM_X2(r, addr)                                                      \
    asm volatile("ldmatrix.sync.aligned.m8n8.x2.shared.b16 {%0,%1}, [%2];"    \
        : "=r"((r)[0]), "=r"((r)[1]) : "r"(addr))

DINL void mma_s8(uint32_t c[4], const uint32_t a[4], uint32_t b0, uint32_t b1) {
    asm volatile(
        "mma.sync.aligned.m16n8k32.row.col.s32.s8.s8.s32 "
        "{%0,%1,%2,%3}, {%4,%5,%6,%7}, {%8,%9}, {%0,%1,%2,%3};"
        : "+r"(c[0]), "+r"(c[1]), "+r"(c[2]), "+r"(c[3])
        : "r"(a[0]), "r"(a[1]), "r"(a[2]), "r"(a[3]), "r"(b0), "r"(b1));
}
DINL void mma_bf16(float c[4], const uint32_t a[4], uint32_t b0, uint32_t b1) {
    asm volatile(
        "mma.sync.aligned.m16n8k16.row.col.f32.bf16.bf16.f32 "
        "{%0,%1,%2,%3}, {%4,%5,%6,%7}, {%8,%9}, {%0,%1,%2,%3};"
        : "+f"(c[0]), "+f"(c[1]), "+f"(c[2]), "+f"(c[3])
        : "r"(a[0]), "r"(a[1]), "r"(a[2]), "r"(a[3]), "r"(b0), "r"(b1));
}

// ============================================================================
// Prep kernels: binarize + tile + SW128-swizzle into scratch
// Swizzle: within a 128B row, 16B chunk c stored at chunk (c ^ (row&7)).
// ============================================================================

// x [8192,4096] f32 -> g_A1 s8 A-blocks (mt*32+ks): 128 rows x 128B
__global__ void prep_actA(const float* __restrict__ x) {
    size_t t = (size_t)blockIdx.x * 256 + threadIdx.x;   // 2,097,152
    int c  = (int)(t & 7);
    int r  = (int)((t >> 3) & 127);
    int ks = (int)((t >> 10) & 31);
    int mt = (int)(t >> 15);
    const float4* s = (const float4*)(x + ((size_t)(mt * 128 + r) * 4096 + ks * 128 + c * 16));
    float4 f0 = s[0], f1 = s[1], f2 = s[2], f3 = s[3];
    uint4 o;
    o.x = pack4s8(f0.x, f0.y, f0.z, f0.w);
    o.y = pack4s8(f1.x, f1.y, f1.z, f1.w);
    o.z = pack4s8(f2.x, f2.y, f2.z, f2.w);
    o.w = pack4s8(f3.x, f3.y, f3.z, f3.w);
    *(uint4*)(g_A1 + ((size_t)(mt * 32 + ks) * 128 + r) * 128 + (((c ^ (r & 7)) << 4))) = o;
}

// w [4096,4096] f32 -> s8 B-blocks (nt*32+ks): 256 rows x 128B
template <int SEL>
__global__ void prep_w(const float* __restrict__ w) {
    size_t t = (size_t)blockIdx.x * 256 + threadIdx.x;   // 1,048,576
    int c  = (int)(t & 7);
    int r  = (int)((t >> 3) & 255);
    int ks = (int)((t >> 11) & 31);
    int nt = (int)(t >> 16);
    const float4* s = (const float4*)(w + ((size_t)(nt * 256 + r) * 4096 + ks * 128 + c * 16));
    float4 f0 = s[0], f1 = s[1], f2 = s[2], f3 = s[3];
    uint4 o;
    o.x = pack4s8(f0.x, f0.y, f0.z, f0.w);
    o.y = pack4s8(f1.x, f1.y, f1.z, f1.w);
    o.z = pack4s8(f2.x, f2.y, f2.z, f2.w);
    o.w = pack4s8(f3.x, f3.y, f3.z, f3.w);
    uint8_t* base = (SEL == 0) ? g_W1 : g_W2;
    *(uint4*)(base + ((size_t)(nt * 32 + ks) * 256 + r) * 128 + (((c ^ (r & 7)) << 4))) = o;
}

// w3 [1000,4096] f32 -> bf16 hi|lo B-blocks (nt*128+ks): 256 rows x 128B.
// Folded K bytes: [0,8192)=hi bf16 of w3, [8192,16384)=lo residual bf16.
__global__ void prep_w3k(const float* __restrict__ w3) {
    size_t t = (size_t)blockIdx.x * 256 + threadIdx.x;   // 1,048,576
    int c  = (int)(t & 7);
    int r  = (int)((t >> 3) & 255);
    int ks = (int)((t >> 11) & 127);
    int nt = (int)(t >> 18);
    int n  = nt * 256 + r;
    int kb = ks * 128 + c * 16;                 // folded K byte offset
    bool hi = kb < 8192;
    int ke = (hi ? kb : kb - 8192) >> 1;        // source k element (8 of them)
    float f[8];
    if (n < 1000) {
        const float4* s = (const float4*)(w3 + (size_t)n * 4096 + ke);
        float4 a = s[0], b = s[1];
        f[0] = a.x; f[1] = a.y; f[2] = a.z; f[3] = a.w;
        f[4] = b.x; f[5] = b.y; f[6] = b.z; f[7] = b.w;
    } else {
        #pragma unroll
        for (int i = 0; i < 8; i++) f[i] = 0.0f;
    }
    uint32_t hwd[8];
    #pragma unroll
    for (int i = 0; i < 8; i++) {
        __nv_bfloat16 h = __float2bfloat16(f[i]);
        if (hi) hwd[i] = (uint32_t)__bfloat16_as_ushort(h);
        else    hwd[i] = (uint32_t)__bfloat16_as_ushort(__float2bfloat16(f[i] - __bfloat162float(h)));
    }
    uint4 o;
    o.x = hwd[0] | (hwd[1] << 16); o.y = hwd[2] | (hwd[3] << 16);
    o.z = hwd[4] | (hwd[5] << 16); o.w = hwd[6] | (hwd[7] << 16);
    *(uint4*)(g_B3 + ((size_t)(nt * 128 + ks) * 256 + r) * 128 + (((c ^ (r & 7)) << 4))) = o;
}

// ============================================================================
// GEMM: CTA 128x256, 8 warps (2m x 4n), warp tile 64x64.
// Stage = 128 K-bytes: A block 16KB + B block 32KB via cp.async.bulk.
// MODE 0: s8,  A=g_A1, B=g_W1, KSTG=32,  out sign(+b1) -> g_A2 (s8 A-layout)
// MODE 1: s8,  A=g_A2, B=g_W2, KSTG=32,  out sign(+b2) -> g_A3 (bf16 A-layout)
// MODE 2: bf16,A=g_A3 (ks&63), B=g_B3, KSTG=128, out acc+b3 -> float [8192,1000]
// ============================================================================
static const int STAGE_BYTES = 49152;            // 16K A + 32K B
static const int NSTAGE      = 4;
static const int CTRL_OFF    = NSTAGE * STAGE_BYTES;          // 196608
static const int SMEM_BYTES  = CTRL_OFF + 64 + 1024;          // mbar + bias

template <int MODE>
__global__ void __launch_bounds__(256, 1) gemm_k(const float* __restrict__ bias,
                                                 float* __restrict__ outf) {
    constexpr int KSTG = (MODE == 2) ? 128 : 32;

    extern __shared__ __align__(128) uint8_t smem[];
    const int tid  = threadIdx.x;
    const int lane = tid & 31;
    const int wid  = tid >> 5;
    const int mt = blockIdx.x, nt = blockIdx.y;
    const int m_w = (wid >> 2) * 64;           // warp M offset (0/64)
    const int n_w = (wid & 3) * 64;            // warp N offset (0..192)
    const uint32_t sbase = smem_u32(smem);
    const uint32_t mbar  = sbase + CTRL_OFF;
    float* s_bias = (float*)(smem + CTRL_OFF + 64);

    const uint8_t* Abase = (MODE == 0) ? g_A1 : (MODE == 1) ? g_A2 : g_A3;
    const uint8_t* Bbase = (MODE == 0) ? g_W1 : (MODE == 1) ? g_W2 : g_B3;
    const uint8_t* Ablk  = Abase + (size_t)mt * ((MODE == 2) ? 64 : 32) * 16384;
    const uint8_t* Bblk  = Bbase + (size_t)nt * KSTG * 32768;

    if (tid == 0) {
        #pragma unroll
        for (int s = 0; s < NSTAGE; s++) MBAR_INIT(mbar + 8 * s, 1);
    }
    {
        int n = nt * 256 + tid;
        s_bias[tid] = (MODE == 2) ? ((n < 1000) ? bias[n] : 0.0f) : bias[n];
    }
    __syncthreads();

    auto issue = [&](int ks) {
        if (tid == 0) {
            const int sl = ks & 3;
            const uint32_t mb = mbar + 8 * sl;
            MBAR_EXPECT_TX(mb, STAGE_BYTES);
            const uint8_t* As = (MODE == 2) ? Ablk + (size_t)(ks & 63) * 16384
                                            : Ablk + (size_t)ks * 16384;
            BULK_G2S(sbase + sl * STAGE_BYTES,         As,                          16384, mb);
            BULK_G2S(sbase + sl * STAGE_BYTES + 16384, Bblk + (size_t)ks * 32768,   32768, mb);
        }
    };

    uint32_t ci[4][8][4];
    float    cf[4][8][4];
    if constexpr (MODE < 2) {
        #pragma unroll
        for (int a = 0; a < 4; a++)
            #pragma unroll
            for (int b = 0; b < 8; b++)
                #pragma unroll
                for (int q = 0; q < 4; q++) ci[a][b][q] = 0u;
    } else {
        #pragma unroll
        for (int a = 0; a < 4; a++)
            #pragma unroll
            for (int b = 0; b < 8; b++)
                #pragma unroll
                for (int q = 0; q < 4; q++) cf[a][b][q] = 0.0f;
    }

    #pragma unroll
    for (int s = 0; s < NSTAGE; s++) issue(s);

    // Per-lane ldmatrix address components (row part precomputed)
    const uint32_t a_row = (uint32_t)(m_w + ((lane >> 3) & 1) * 8 + (lane & 7));
    const uint32_t a_chi = (uint32_t)(lane >> 4);          // 16B chunk sub-index
    const uint32_t b_row = (uint32_t)(n_w + (lane & 7));
    const uint32_t b_chi = (uint32_t)((lane >> 3) & 1);

    #pragma unroll 1
    for (int ks = 0; ks < KSTG; ks++) {
        const int sl = ks & 3;
        MBAR_WAIT(mbar + 8 * sl, (ks >> 2) & 1);
        const uint32_t sA = sbase + sl * STAGE_BYTES;
        const uint32_t sB = sA + 16384;

        #pragma unroll
        for (int kst = 0; kst < 4; kst++) {
            uint32_t a[4][4];
            #pragma unroll
            for (int mi = 0; mi < 4; mi++) {
                uint32_t rl = a_row + mi * 16;
                uint32_t c  = (uint32_t)(kst * 2) + a_chi;
                LDSM_X4(a[mi], sA + rl * 128 + (((c ^ (rl & 7)) << 4)));
            }
            uint32_t b[8][2];
            #pragma unroll
            for (int ni = 0; ni < 8; ni++) {
                uint32_t rl = b_row + ni * 8;
                uint32_t c  = (uint32_t)(kst * 2) + b_chi;
                LDSM_X2(b[ni], sB + rl * 128 + (((c ^ (rl & 7)) << 4)));
            }
            #pragma unroll
            for (int mi = 0; mi < 4; mi++)
                #pragma unroll
                for (int ni = 0; ni < 8; ni++) {
                    if constexpr (MODE < 2)
                        mma_s8(ci[mi][ni], a[mi], b[ni][0], b[ni][1]);
                    else
                        mma_bf16(cf[mi][ni], a[mi], b[ni][0], b[ni][1]);
                }
        }
        __syncthreads();                      // all warps done reading slot
        if (ks + NSTAGE < KSTG) issue(ks + NSTAGE);
    }

    // ---------------- epilogue ----------------
    const int g = lane >> 2, t4 = lane & 3;
    #pragma unroll
    for (int mi = 0; mi < 4; mi++) {
        const int rl0 = m_w + mi * 16 + g;               // local rows rl0, rl0+8
        #pragma unroll
        for (int ni = 0; ni < 8; ni++) {
            const int nl = n_w + ni * 8 + t4 * 2;        // local cols nl, nl+1
            const int ng = nt * 256 + nl;
            const float b0 = s_bias[nl], b1 = s_bias[nl + 1];
            if constexpr (MODE == 0) {
                float f0 = (float)(int)ci[mi][ni][0] + b0;
                float f1 = (float)(int)ci[mi][ni][1] + b1;
                float f2 = (float)(int)ci[mi][ni][2] + b0;
                float f3 = (float)(int)ci[mi][ni][3] + b1;
                uint16_t p0 = (uint16_t)(s8byte(f0) | (s8byte(f1) << 8));
                uint16_t p1 = (uint16_t)(s8byte(f2) | (s8byte(f3) << 8));
                const int ks2 = ng >> 7, koff = ng & 127;
                const uint32_t sw = (uint32_t)koff & 15u;
                uint8_t* blk = g_A2 + (size_t)(mt * 32 + ks2) * 16384;
                uint32_t o0 = (uint32_t)rl0 * 128 + ((((uint32_t)(koff >> 4) ^ ((uint32_t)rl0 & 7)) << 4) | sw);
                uint32_t o1 = (uint32_t)(rl0 + 8) * 128 + ((((uint32_t)(koff >> 4) ^ ((uint32_t)(rl0 + 8) & 7)) << 4) | sw);
                *(uint16_t*)(blk + o0) = p0;
                *(uint16_t*)(blk + o1) = p1;
            } else if constexpr (MODE == 1) {
                float f0 = (float)(int)ci[mi][ni][0] + b0;
                float f1 = (float)(int)ci[mi][ni][1] + b1;
                float f2 = (float)(int)ci[mi][ni][2] + b0;
                float f3 = (float)(int)ci[mi][ni][3] + b1;
                uint32_t p0 = bf16sgn(f0) | (bf16sgn(f1) << 16);
                uint32_t p1 = bf16sgn(f2) | (bf16sgn(f3) << 16);
                const int nb = ng * 2;                    // byte offset in bf16 row
                const int ks2 = nb >> 7, koff = nb & 127;
                const uint32_t sw = (uint32_t)koff & 15u;
                uint8_t* blk = g_A3 + (size_t)(mt * 64 + ks2) * 16384;
                uint32_t o0 = (uint32_t)rl0 * 128 + ((((uint32_t)(koff >> 4) ^ ((uint32_t)rl0 & 7)) << 4) | sw);
                uint32_t o1 = (uint32_t)(rl0 + 8) * 128 + ((((uint32_t)(koff >> 4) ^ ((uint32_t)(rl0 + 8) & 7)) << 4) | sw);
                *(uint32_t*)(blk + o0) = p0;
                *(uint32_t*)(blk + o1) = p1;
            } else {
                const size_t r0 = (size_t)(mt * 128 + rl0);
                float f0 = cf[mi][ni][0] + b0;
                float f1 = cf[mi][ni][1] + b1;
                float f2 = cf[mi][ni][2] + b0;
                float f3 = cf[mi][ni][3] + b1;
                if (ng < 1000) {
                    outf[r0 * 1000 + ng]       = f0;
                    outf[(r0 + 8) * 1000 + ng] = f2;
                }
                if (ng + 1 < 1000) {
                    outf[r0 * 1000 + ng + 1]       = f1;
                    outf[(r0 + 8) * 1000 + ng + 1] = f3;
                }
            }
        }
    }
}

// ============================================================================
// kernel_launch
// ============================================================================
extern "C" void kernel_launch(void* const* d_in, const int* in_sizes, int n_in,
                              void* d_out, int out_size) {
    (void)in_sizes; (void)n_in; (void)out_size;
    const float* x  = (const float*)d_in[0];
    const float* w1 = (const float*)d_in[1];
    const float* b1 = (const float*)d_in[2];
    const float* w2 = (const float*)d_in[3];
    const float* b2 = (const float*)d_in[4];
    const float* w3 = (const float*)d_in[5];
    const float* b3 = (const float*)d_in[6];
    float* out = (float*)d_out;

    cudaFuncSetAttribute(gemm_k<0>, cudaFuncAttributeMaxDynamicSharedMemorySize, SMEM_BYTES);
    cudaFuncSetAttribute(gemm_k<1>, cudaFuncAttributeMaxDynamicSharedMemorySize, SMEM_BYTES);
    cudaFuncSetAttribute(gemm_k<2>, cudaFuncAttributeMaxDynamicSharedMemorySize, SMEM_BYTES);

    prep_actA<<<8192, 256>>>(x);
    prep_w<0><<<4096, 256>>>(w1);
    prep_w<1><<<4096, 256>>>(w2);
    prep_w3k<<<4096, 256>>>(w3);

    gemm_k<0><<<dim3(64, 16), 256, SMEM_BYTES>>>(b1, nullptr);
    gemm_k<1><<<dim3(64, 16), 256, SMEM_BYTES>>>(b2, nullptr);
    gemm_k<2><<<dim3(64, 4),  256, SMEM_BYTES>>>(b3, out);
}

// round 6
// speedup vs baseline: 1.1371x; 1.0564x over previous
#include <cuda_runtime.h>
#include <cuda_bf16.h>
#include <cstdint>

// ============================================================================
// SimpleBNN on GB300 — sm_103 (non-'a': no tcgen05; mma.sync is EMULATED).
// Layers 1/2: XOR-POPC bit-GEMM (exact ternary via sign+mask bitplanes):
//   dot(m,n) = C0[m] - 2 * sum_words popc( (sa ^ sb) & za )
// Layer 3:    bf16 mma.sync GEMM, w3 = hi+lo split folded into K=8192.
// ============================================================================

#define DINL __device__ __forceinline__

// ---------------- device scratch ----------------
// Bit blocks: (tile*4 + ks) of 128 rows x 128B (32 u32 words = 1024 K-bits),
// 16B chunk c stored at position c ^ ((row>>3)&7)  [bank-conflict-free LDS128]
__device__ __align__(128) uint8_t g_A1s[(size_t)64 * 4 * 16384];  // sign(x) bits
__device__ __align__(128) uint8_t g_A1m[(size_t)64 * 4 * 16384];  // x != 0 bits
__device__ __align__(128) uint8_t g_W1b[(size_t)32 * 4 * 16384];  // sign(w1) bits
__device__ __align__(128) uint8_t g_W2b[(size_t)32 * 4 * 16384];  // sign(w2) bits
__device__ __align__(128) uint8_t g_A2s[(size_t)64 * 4 * 16384];  // sign(a1) bits
__device__ __align__(128) uint8_t g_A2m[(size_t)64 * 4 * 16384];  // a1 != 0 bits
__device__ int g_C0x[8192];                                       // nnz per x row
__device__ int g_C01[8192];                                       // nnz per a1 row
// Layer-3 operands (same layouts as round 5)
__device__ __align__(128) uint8_t g_A3[(size_t)64 * 64 * 16384];  // a2 bf16 A-blocks
__device__ __align__(128) uint8_t g_B3[(size_t)4 * 128 * 32768];  // w3 hi|lo bf16 B-blocks

// ---------------- helpers ----------------
DINL uint32_t smem_u32(const void* p) {
    uint32_t a;
    asm("{ .reg .u64 t; cvta.to.shared.u64 t, %1; cvt.u32.u64 %0, t; }" : "=r"(a) : "l"(p));
    return a;
}
DINL uint4 lds128(uint32_t addr) {
    uint4 v;
    asm volatile("ld.shared.v4.u32 {%0,%1,%2,%3}, [%4];"
                 : "=r"(v.x), "=r"(v.y), "=r"(v.z), "=r"(v.w) : "r"(addr));
    return v;
}
DINL uint32_t bf16sgn(float v) {    // sign -> bf16 bits (+-1.0 or 0)
    uint32_t u = __float_as_uint(v);
    return ((u << 1) == 0u) ? 0u : (0x3F80u | ((u >> 31) << 15));
}

#define MBAR_INIT(addr, cnt) \
    asm volatile("mbarrier.init.shared.b64 [%0], %1;" :: "r"(addr), "r"(cnt) : "memory")
#define MBAR_EXPECT_TX(addr, tx) \
    asm volatile("mbarrier.arrive.expect_tx.shared.b64 _, [%0], %1;" \
                 :: "r"(addr), "r"(tx) : "memory")
#define MBAR_WAIT(addr, parity) do {                                          \
    asm volatile("{\n\t.reg .pred P1;\n\t"                                    \
        "WAIT_%=:\n\t"                                                        \
        "mbarrier.try_wait.parity.acquire.cta.shared::cta.b64 P1, [%0], %1, 0x989680;\n\t" \
        "@P1 bra.uni DONE_%=;\n\t"                                            \
        "bra.uni WAIT_%=;\n\t"                                                \
        "DONE_%=:\n\t}"                                                       \
        :: "r"((uint32_t)(addr)), "r"((uint32_t)(parity)) : "memory");        \
} while (0)
#define BULK_G2S(dst, src, bytes, mbar)                                       \
    asm volatile("cp.async.bulk.shared::cluster.global.mbarrier::complete_tx::bytes " \
                 "[%0], [%1], %2, [%3];"                                      \
                 :: "r"((uint32_t)(dst)), "l"(src), "r"((uint32_t)(bytes)),   \
                    "r"((uint32_t)(mbar)) : "memory")

#define LDSM_X4(r, addr)                                                      \
    asm volatile("ldmatrix.sync.aligned.m8n8.x4.shared.b16 {%0,%1,%2,%3}, [%4];" \
        : "=r"((r)[0]), "=r"((r)[1]), "=r"((r)[2]), "=r"((r)[3]) : "r"(addr))
#define LDSM_X2(r, addr)                                                      \
    asm volatile("ldmatrix.sync.aligned.m8n8.x2.shared.b16 {%0,%1}, [%2];"    \
        : "=r"((r)[0]), "=r"((r)[1]) : "r"(addr))

DINL void mma_bf16(float c[4], const uint32_t a[4], uint32_t b0, uint32_t b1) {
    asm volatile(
        "mma.sync.aligned.m16n8k16.row.col.f32.bf16.bf16.f32 "
        "{%0,%1,%2,%3}, {%4,%5,%6,%7}, {%8,%9}, {%0,%1,%2,%3};"
        : "+f"(c[0]), "+f"(c[1]), "+f"(c[2]), "+f"(c[3])
        : "r"(a[0]), "r"(a[1]), "r"(a[2]), "r"(a[3]), "r"(b0), "r"(b1));
}

// ============================================================================
// Prep: pack sign/mask bitplanes, tiled + chunk-swizzled for bulk copy
// ============================================================================
template <int SEL>   // 0: x -> A1s/A1m ; 1: w1 -> W1b ; 2: w2 -> W2b
__global__ void pack_bits(const float* __restrict__ src) {
    uint32_t t = blockIdx.x * 256 + threadIdx.x;     // rows*128 threads
    uint32_t row = t >> 7, w = t & 127;
    const float* p = src + (size_t)row * 4096 + w * 32;
    uint32_t s = 0, m = 0;
    #pragma unroll
    for (int j = 0; j < 32; j += 4) {
        float4 f = *(const float4*)(p + j);
        uint32_t u0 = __float_as_uint(f.x), u1 = __float_as_uint(f.y);
        uint32_t u2 = __float_as_uint(f.z), u3 = __float_as_uint(f.w);
        s |= (u0 >> 31) << j | (u1 >> 31) << (j + 1)
           | (u2 >> 31) << (j + 2) | (u3 >> 31) << (j + 3);
        m |= (uint32_t)((u0 << 1) != 0) << j       | (uint32_t)((u1 << 1) != 0) << (j + 1)
           | (uint32_t)((u2 << 1) != 0) << (j + 2) | (uint32_t)((u3 << 1) != 0) << (j + 3);
    }
    uint32_t rt = row >> 7, r = row & 127, ks = w >> 5, wi = w & 31;
    size_t off = ((size_t)(rt * 4 + ks) * 128 + r) * 128
               + (((wi >> 2) ^ ((r >> 3) & 7)) << 4) + (wi & 3) * 4;
    if (SEL == 0) { *(uint32_t*)(g_A1s + off) = s; *(uint32_t*)(g_A1m + off) = m; }
    else if (SEL == 1) { *(uint32_t*)(g_W1b + off) = s; }
    else               { *(uint32_t*)(g_W2b + off) = s; }
}

// C0[m] = number of nonzero entries in A row m (popc over mask plane)
template <int SEL>   // 0: g_A1m -> g_C0x ; 1: g_A2m -> g_C01
__global__ void c0_kernel() {
    int m = blockIdx.x * 256 + threadIdx.x;          // 8192 threads
    const uint8_t* base = SEL ? g_A2m : g_A1m;
    int rt = m >> 7, r = m & 127, cnt = 0;
    #pragma unroll
    for (int ks = 0; ks < 4; ks++) {
        const uint4* rowp = (const uint4*)(base + ((size_t)(rt * 4 + ks) * 128 + r) * 128);
        #pragma unroll
        for (int c2 = 0; c2 < 8; c2++) {
            uint4 v = rowp[c2];
            cnt += __popc(v.x) + __popc(v.y) + __popc(v.z) + __popc(v.w);
        }
    }
    if (SEL) g_C01[m] = cnt; else g_C0x[m] = cnt;
}

// w3 [1000,4096] f32 -> bf16 hi|lo B-blocks (nt*128+ks): 256 rows x 128B (round-5 layout)
__global__ void prep_w3k(const float* __restrict__ w3) {
    size_t t = (size_t)blockIdx.x * 256 + threadIdx.x;   // 1,048,576
    int c  = (int)(t & 7);
    int r  = (int)((t >> 3) & 255);
    int ks = (int)((t >> 11) & 127);
    int nt = (int)(t >> 18);
    int n  = nt * 256 + r;
    int kb = ks * 128 + c * 16;
    bool hi = kb < 8192;
    int ke = (hi ? kb : kb - 8192) >> 1;
    float f[8];
    if (n < 1000) {
        const float4* s = (const float4*)(w3 + (size_t)n * 4096 + ke);
        float4 a = s[0], b = s[1];
        f[0] = a.x; f[1] = a.y; f[2] = a.z; f[3] = a.w;
        f[4] = b.x; f[5] = b.y; f[6] = b.z; f[7] = b.w;
    } else {
        #pragma unroll
        for (int i = 0; i < 8; i++) f[i] = 0.0f;
    }
    uint32_t hwd[8];
    #pragma unroll
    for (int i = 0; i < 8; i++) {
        __nv_bfloat16 h = __float2bfloat16(f[i]);
        if (hi) hwd[i] = (uint32_t)__bfloat16_as_ushort(h);
        else    hwd[i] = (uint32_t)__bfloat16_as_ushort(__float2bfloat16(f[i] - __bfloat162float(h)));
    }
    uint4 o;
    o.x = hwd[0] | (hwd[1] << 16); o.y = hwd[2] | (hwd[3] << 16);
    o.z = hwd[4] | (hwd[5] << 16); o.w = hwd[6] | (hwd[7] << 16);
    *(uint4*)(g_B3 + ((size_t)(nt * 128 + ks) * 256 + r) * 128 + (((c ^ (r & 7)) << 4))) = o;
}

// ============================================================================
// bit-GEMM: CTA 128x128, 8 warps (2m x 4n, warp 64x32), lane tile 8m x 8n.
// K = 4096 bits in 4 stages of 1024 bits (A sign 16KB + A mask 16KB + B 16KB).
// LAYER 1: out = {sign,mask} bits of (dot + b1) -> g_A2s/g_A2m
// LAYER 2: out = bf16 sign of (dot + b2)        -> g_A3 (layer-3 A layout)
// ============================================================================
static const int BG_STAGE = 49152;
static const int BG_SMEM  = 4 * BG_STAGE + 64;

template <int LAYER>
__global__ void __launch_bounds__(256, 1) bitgemm(const float* __restrict__ bias) {
    extern __shared__ __align__(128) uint8_t smem[];
    const int tid = threadIdx.x, lane = tid & 31;
    const int wid = tid >> 5;
    const int g = lane >> 2, c = lane & 3;
    const int mt = blockIdx.x, nt = blockIdx.y;
    const int warp_m = (wid >> 2) * 64, warp_n = (wid & 3) * 32;
    const uint32_t sb = smem_u32(smem);
    const uint32_t mbar = sb + 4 * BG_STAGE;

    const uint8_t* As = (LAYER == 1) ? g_A1s : g_A2s;
    const uint8_t* Am = (LAYER == 1) ? g_A1m : g_A2m;
    const uint8_t* Bs = (LAYER == 1) ? g_W1b : g_W2b;
    const int*     C0 = (LAYER == 1) ? g_C0x : g_C01;

    if (tid == 0) {
        #pragma unroll
        for (int s = 0; s < 4; s++) MBAR_INIT(mbar + 8 * s, 1);
    }
    __syncthreads();
    if (tid == 0) {
        #pragma unroll
        for (int ks = 0; ks < 4; ks++) {
            const uint32_t mb = mbar + 8 * ks;
            MBAR_EXPECT_TX(mb, BG_STAGE);
            BULK_G2S(sb + ks * BG_STAGE,         As + (size_t)(mt * 4 + ks) * 16384, 16384, mb);
            BULK_G2S(sb + ks * BG_STAGE + 16384, Am + (size_t)(mt * 4 + ks) * 16384, 16384, mb);
            BULK_G2S(sb + ks * BG_STAGE + 32768, Bs + (size_t)(nt * 4 + ks) * 16384, 16384, mb);
        }
    }

    int acc[8][8];
    #pragma unroll
    for (int i = 0; i < 8; i++)
        #pragma unroll
        for (int j = 0; j < 8; j++) acc[i][j] = 0;

    #pragma unroll 1
    for (int ks = 0; ks < 4; ks++) {
        MBAR_WAIT(mbar + 8 * ks, 0);
        const uint32_t sA = sb + ks * BG_STAGE;
        const uint32_t sM = sA + 16384;
        const uint32_t sBs = sA + 32768;
        #pragma unroll
        for (int kc = 0; kc < 8; kc++) {
            uint4 bv[8];
            #pragma unroll
            for (int nj = 0; nj < 8; nj++) {
                uint32_t br = (uint32_t)(warp_n + c * 8 + nj);
                bv[nj] = lds128(sBs + br * 128 + (((uint32_t)kc ^ ((br >> 3) & 7)) << 4));
            }
            #pragma unroll
            for (int mi = 0; mi < 8; mi++) {
                uint32_t ar = (uint32_t)(warp_m + g * 8 + mi);
                uint32_t sw = (((uint32_t)kc ^ ((ar >> 3) & 7)) << 4);
                uint4 av = lds128(sA + ar * 128 + sw);
                uint4 mv = lds128(sM + ar * 128 + sw);
                #pragma unroll
                for (int nj = 0; nj < 8; nj++) {
                    acc[mi][nj] += __popc((av.x ^ bv[nj].x) & mv.x)
                                 + __popc((av.y ^ bv[nj].y) & mv.y)
                                 + __popc((av.z ^ bv[nj].z) & mv.z)
                                 + __popc((av.w ^ bv[nj].w) & mv.w);
                }
            }
        }
    }

    // ---------------- epilogue ----------------
    float bn[8];
    #pragma unroll
    for (int nj = 0; nj < 8; nj++) bn[nj] = bias[nt * 128 + warp_n + c * 8 + nj];

    #pragma unroll
    for (int mi = 0; mi < 8; mi++) {
        const int rl = warp_m + g * 8 + mi;
        const int m  = mt * 128 + rl;
        const int c0 = C0[m];
        float v[8];
        #pragma unroll
        for (int nj = 0; nj < 8; nj++) v[nj] = (float)(c0 - 2 * acc[mi][nj]) + bn[nj];

        if (LAYER == 1) {
            uint32_t bs_ = 0, bm_ = 0;
            #pragma unroll
            for (int nj = 0; nj < 8; nj++) {
                uint32_t u = __float_as_uint(v[nj]);
                bs_ |= (u >> 31) << nj;
                bm_ |= (uint32_t)((u << 1) != 0) << nj;
            }
            uint32_t ws = bs_ << (8 * c), wm = bm_ << (8 * c);
            ws |= __shfl_xor_sync(0xFFFFFFFFu, ws, 1);
            ws |= __shfl_xor_sync(0xFFFFFFFFu, ws, 2);
            wm |= __shfl_xor_sync(0xFFFFFFFFu, wm, 1);
            wm |= __shfl_xor_sync(0xFFFFFFFFu, wm, 2);
            if (c == 0) {
                int nw = nt * 4 + (warp_n >> 5);        // global 32-bit word index
                int ks2 = nw >> 5, wi = nw & 31;
                size_t off = ((size_t)(mt * 4 + ks2) * 128 + rl) * 128
                           + (((wi >> 2) ^ ((rl >> 3) & 7)) << 4) + (wi & 3) * 4;
                *(uint32_t*)(g_A2s + off) = ws;
                *(uint32_t*)(g_A2m + off) = wm;
            }
        } else {
            uint32_t pk[4];
            #pragma unroll
            for (int q = 0; q < 4; q++)
                pk[q] = bf16sgn(v[2 * q]) | (bf16sgn(v[2 * q + 1]) << 16);
            const int n0 = nt * 128 + warp_n + c * 8;
            const int nb = n0 * 2;                       // byte offset in 8192B row
            size_t off = ((size_t)(mt * 64 + (nb >> 7)) * 128 + rl) * 128
                       + ((((uint32_t)(nb >> 4) & 7) ^ ((uint32_t)rl & 7)) << 4);
            *(uint4*)(g_A3 + off) = make_uint4(pk[0], pk[1], pk[2], pk[3]);
        }
    }
}

// ============================================================================
// Layer-3 bf16 GEMM (round-5 MODE 2, unchanged): CTA 128x256, K=8192 (hi|lo)
// ============================================================================
static const int G3_STAGE = 49152;
static const int G3_SMEM  = 4 * G3_STAGE + 64 + 1024;

__global__ void __launch_bounds__(256, 1) gemm3(const float* __restrict__ bias,
                                                float* __restrict__ outf) {
    extern __shared__ __align__(128) uint8_t smem[];
    const int tid = threadIdx.x, lane = tid & 31, wid = tid >> 5;
    const int mt = blockIdx.x, nt = blockIdx.y;
    const int m_w = (wid >> 2) * 64, n_w = (wid & 3) * 64;
    const uint32_t sbase = smem_u32(smem);
    const uint32_t mbar  = sbase + 4 * G3_STAGE;
    float* s_bias = (float*)(smem + 4 * G3_STAGE + 64);

    const uint8_t* Ablk = g_A3 + (size_t)mt * 64 * 16384;
    const uint8_t* Bblk = g_B3 + (size_t)nt * 128 * 32768;

    if (tid == 0) {
        #pragma unroll
        for (int s = 0; s < 4; s++) MBAR_INIT(mbar + 8 * s, 1);
    }
    {
        int n = nt * 256 + tid;
        s_bias[tid] = (n < 1000) ? bias[n] : 0.0f;
    }
    __syncthreads();

    auto issue = [&](int ks) {
        if (tid == 0) {
            const int sl = ks & 3;
            const uint32_t mb = mbar + 8 * sl;
            MBAR_EXPECT_TX(mb, G3_STAGE);
            BULK_G2S(sbase + sl * G3_STAGE,         Ablk + (size_t)(ks & 63) * 16384, 16384, mb);
            BULK_G2S(sbase + sl * G3_STAGE + 16384, Bblk + (size_t)ks * 32768,        32768, mb);
        }
    };

    float cf[4][8][4];
    #pragma unroll
    for (int a = 0; a < 4; a++)
        #pragma unroll
        for (int b = 0; b < 8; b++)
            #pragma unroll
            for (int q = 0; q < 4; q++) cf[a][b][q] = 0.0f;

    #pragma unroll
    for (int s = 0; s < 4; s++) issue(s);

    const uint32_t a_row = (uint32_t)(m_w + ((lane >> 3) & 1) * 8 + (lane & 7));
    const uint32_t a_chi = (uint32_t)(lane >> 4);
    const uint32_t b_row = (uint32_t)(n_w + (lane & 7));
    const uint32_t b_chi = (uint32_t)((lane >> 3) & 1);

    #pragma unroll 1
    for (int ks = 0; ks < 128; ks++) {
        const int sl = ks & 3;
        MBAR_WAIT(mbar + 8 * sl, (ks >> 2) & 1);
        const uint32_t sA = sbase + sl * G3_STAGE;
        const uint32_t sB = sA + 16384;

        #pragma unroll
        for (int kst = 0; kst < 4; kst++) {
            uint32_t a[4][4];
            #pragma unroll
            for (int mi = 0; mi < 4; mi++) {
                uint32_t rl = a_row + mi * 16;
                uint32_t cc = (uint32_t)(kst * 2) + a_chi;
                LDSM_X4(a[mi], sA + rl * 128 + (((cc ^ (rl & 7)) << 4)));
            }
            uint32_t b[8][2];
            #pragma unroll
            for (int ni = 0; ni < 8; ni++) {
                uint32_t rl = b_row + ni * 8;
                uint32_t cc = (uint32_t)(kst * 2) + b_chi;
                LDSM_X2(b[ni], sB + rl * 128 + (((cc ^ (rl & 7)) << 4)));
            }
            #pragma unroll
            for (int mi = 0; mi < 4; mi++)
                #pragma unroll
                for (int ni = 0; ni < 8; ni++)
                    mma_bf16(cf[mi][ni], a[mi], b[ni][0], b[ni][1]);
        }
        __syncthreads();
        if (ks + 4 < 128) issue(ks + 4);
    }

    const int g = lane >> 2, t4 = lane & 3;
    #pragma unroll
    for (int mi = 0; mi < 4; mi++) {
        const int rl0 = m_w + mi * 16 + g;
        #pragma unroll
        for (int ni = 0; ni < 8; ni++) {
            const int nl = n_w + ni * 8 + t4 * 2;
            const int ng = nt * 256 + nl;
            const size_t r0 = (size_t)(mt * 128 + rl0);
            float f0 = cf[mi][ni][0] + s_bias[nl];
            float f1 = cf[mi][ni][1] + s_bias[nl + 1];
            float f2 = cf[mi][ni][2] + s_bias[nl];
            float f3 = cf[mi][ni][3] + s_bias[nl + 1];
            if (ng < 1000) {
                outf[r0 * 1000 + ng]       = f0;
                outf[(r0 + 8) * 1000 + ng] = f2;
            }
            if (ng + 1 < 1000) {
                outf[r0 * 1000 + ng + 1]       = f1;
                outf[(r0 + 8) * 1000 + ng + 1] = f3;
            }
        }
    }
}

// ============================================================================
// kernel_launch — ordered so kernel-launch index 3 (the one ncu captures)
// is bitgemm<1>.
// ============================================================================
extern "C" void kernel_launch(void* const* d_in, const int* in_sizes, int n_in,
                              void* d_out, int out_size) {
    (void)in_sizes; (void)n_in; (void)out_size;
    const float* x  = (const float*)d_in[0];
    const float* w1 = (const float*)d_in[1];
    const float* b1 = (const float*)d_in[2];
    const float* w2 = (const float*)d_in[3];
    const float* b2 = (const float*)d_in[4];
    const float* w3 = (const float*)d_in[5];
    const float* b3 = (const float*)d_in[6];
    float* out = (float*)d_out;

    cudaFuncSetAttribute(bitgemm<1>, cudaFuncAttributeMaxDynamicSharedMemorySize, BG_SMEM);
    cudaFuncSetAttribute(bitgemm<2>, cudaFuncAttributeMaxDynamicSharedMemorySize, BG_SMEM);
    cudaFuncSetAttribute(gemm3,      cudaFuncAttributeMaxDynamicSharedMemorySize, G3_SMEM);

    pack_bits<0><<<4096, 256>>>(x);                       // 0
    pack_bits<1><<<2048, 256>>>(w1);                      // 1
    c0_kernel<0><<<32, 256>>>();                          // 2
    bitgemm<1><<<dim3(64, 32), 256, BG_SMEM>>>(b1);       // 3  <- profiled
    pack_bits<2><<<2048, 256>>>(w2);                      // 4
    c0_kernel<1><<<32, 256>>>();                          // 5
    bitgemm<2><<<dim3(64, 32), 256, BG_SMEM>>>(b2);       // 6
    prep_w3k<<<4096, 256>>>(w3);                          // 7
    gemm3<<<dim3(64, 4), 256, G3_SMEM>>>(b3, out);        // 8
}

// round 7
// speedup vs baseline: 1.9452x; 1.7108x over previous
#include <cuda_runtime.h>
#include <cuda_bf16.h>
#include <cstdint>

// ============================================================================
// SimpleBNN on GB300 — sm_103 (non-'a': no tcgen05; mma.sync is EMULATED).
// Layers 1/2: XOR-POPC bit-GEMM (exact ternary via sign+mask bitplanes):
//   dot(m,n) = C0[m] - 2 * sum_words popc( (sa ^ sb) & za )
//   Round 7: packed 16-bit accumulators + XOR swizzle addressing + 2 CTAs/SM.
// Layer 3:    bf16 mma.sync GEMM, w3 = hi+lo split folded into K=8192.
// ============================================================================

#define DINL __device__ __forceinline__

// ---------------- device scratch ----------------
// Bit blocks: (tile*4 + ks) of 128 rows x 128B (32 u32 words = 1024 K-bits),
// 16B chunk c stored at position c ^ ((row>>3)&7)  [bank-conflict-free LDS128]
__device__ __align__(128) uint8_t g_A1s[(size_t)64 * 4 * 16384];  // sign(x) bits
__device__ __align__(128) uint8_t g_A1m[(size_t)64 * 4 * 16384];  // x != 0 bits
__device__ __align__(128) uint8_t g_W1b[(size_t)32 * 4 * 16384];  // sign(w1) bits
__device__ __align__(128) uint8_t g_W2b[(size_t)32 * 4 * 16384];  // sign(w2) bits
__device__ __align__(128) uint8_t g_A2s[(size_t)64 * 4 * 16384];  // sign(a1) bits
__device__ __align__(128) uint8_t g_A2m[(size_t)64 * 4 * 16384];  // a1 != 0 bits
__device__ int g_C0x[8192];                                       // nnz per x row
__device__ int g_C01[8192];                                       // nnz per a1 row
// Layer-3 operands
__device__ __align__(128) uint8_t g_A3[(size_t)64 * 64 * 16384];  // a2 bf16 A-blocks
__device__ __align__(128) uint8_t g_B3[(size_t)4 * 128 * 32768];  // w3 hi|lo bf16 B-blocks

// ---------------- helpers ----------------
DINL uint32_t smem_u32(const void* p) {
    uint32_t a;
    asm("{ .reg .u64 t; cvta.to.shared.u64 t, %1; cvt.u32.u64 %0, t; }" : "=r"(a) : "l"(p));
    return a;
}
DINL uint4 lds128(uint32_t addr) {
    uint4 v;
    asm volatile("ld.shared.v4.u32 {%0,%1,%2,%3}, [%4];"
                 : "=r"(v.x), "=r"(v.y), "=r"(v.z), "=r"(v.w) : "r"(addr));
    return v;
}
DINL uint32_t bf16sgn(float v) {    // sign -> bf16 bits (+-1.0 or 0)
    uint32_t u = __float_as_uint(v);
    return ((u << 1) == 0u) ? 0u : (0x3F80u | ((u >> 31) << 15));
}

#define MBAR_INIT(addr, cnt) \
    asm volatile("mbarrier.init.shared.b64 [%0], %1;" :: "r"(addr), "r"(cnt) : "memory")
#define MBAR_EXPECT_TX(addr, tx) \
    asm volatile("mbarrier.arrive.expect_tx.shared.b64 _, [%0], %1;" \
                 :: "r"(addr), "r"(tx) : "memory")
#define MBAR_WAIT(addr, parity) do {                                          \
    asm volatile("{\n\t.reg .pred P1;\n\t"                                    \
        "WAIT_%=:\n\t"                                                        \
        "mbarrier.try_wait.parity.acquire.cta.shared::cta.b64 P1, [%0], %1, 0x989680;\n\t" \
        "@P1 bra.uni DONE_%=;\n\t"                                            \
        "bra.uni WAIT_%=;\n\t"                                                \
        "DONE_%=:\n\t}"                                                       \
        :: "r"((uint32_t)(addr)), "r"((uint32_t)(parity)) : "memory");        \
} while (0)
#define BULK_G2S(dst, src, bytes, mbar)                                       \
    asm volatile("cp.async.bulk.shared::cluster.global.mbarrier::complete_tx::bytes " \
                 "[%0], [%1], %2, [%3];"                                      \
                 :: "r"((uint32_t)(dst)), "l"(src), "r"((uint32_t)(bytes)),   \
                    "r"((uint32_t)(mbar)) : "memory")

#define LDSM_X4(r, addr)                                                      \
    asm volatile("ldmatrix.sync.aligned.m8n8.x4.shared.b16 {%0,%1,%2,%3}, [%4];" \
        : "=r"((r)[0]), "=r"((r)[1]), "=r"((r)[2]), "=r"((r)[3]) : "r"(addr))
#define LDSM_X2(r, addr)                                                      \
    asm volatile("ldmatrix.sync.aligned.m8n8.x2.shared.b16 {%0,%1}, [%2];"    \
        : "=r"((r)[0]), "=r"((r)[1]) : "r"(addr))

DINL void mma_bf16(float c[4], const uint32_t a[4], uint32_t b0, uint32_t b1) {
    asm volatile(
        "mma.sync.aligned.m16n8k16.row.col.f32.bf16.bf16.f32 "
        "{%0,%1,%2,%3}, {%4,%5,%6,%7}, {%8,%9}, {%0,%1,%2,%3};"
        : "+f"(c[0]), "+f"(c[1]), "+f"(c[2]), "+f"(c[3])
        : "r"(a[0]), "r"(a[1]), "r"(a[2]), "r"(a[3]), "r"(b0), "r"(b1));
}

// ============================================================================
// Prep: pack sign/mask bitplanes, tiled + chunk-swizzled for bulk copy
// ============================================================================
template <int SEL>   // 0: x -> A1s/A1m ; 1: w1 -> W1b ; 2: w2 -> W2b
__global__ void pack_bits(const float* __restrict__ src) {
    uint32_t t = blockIdx.x * 256 + threadIdx.x;     // rows*128 threads
    uint32_t row = t >> 7, w = t & 127;
    const float* p = src + (size_t)row * 4096 + w * 32;
    uint32_t s = 0, m = 0;
    #pragma unroll
    for (int j = 0; j < 32; j += 4) {
        float4 f = *(const float4*)(p + j);
        uint32_t u0 = __float_as_uint(f.x), u1 = __float_as_uint(f.y);
        uint32_t u2 = __float_as_uint(f.z), u3 = __float_as_uint(f.w);
        s |= (u0 >> 31) << j | (u1 >> 31) << (j + 1)
           | (u2 >> 31) << (j + 2) | (u3 >> 31) << (j + 3);
        m |= (uint32_t)((u0 << 1) != 0) << j       | (uint32_t)((u1 << 1) != 0) << (j + 1)
           | (uint32_t)((u2 << 1) != 0) << (j + 2) | (uint32_t)((u3 << 1) != 0) << (j + 3);
    }
    uint32_t rt = row >> 7, r = row & 127, ks = w >> 5, wi = w & 31;
    size_t off = ((size_t)(rt * 4 + ks) * 128 + r) * 128
               + (((wi >> 2) ^ ((r >> 3) & 7)) << 4) + (wi & 3) * 4;
    if (SEL == 0) { *(uint32_t*)(g_A1s + off) = s; *(uint32_t*)(g_A1m + off) = m; }
    else if (SEL == 1) { *(uint32_t*)(g_W1b + off) = s; }
    else               { *(uint32_t*)(g_W2b + off) = s; }
}

// C0[m] = number of nonzero entries in A row m (popc over mask plane)
template <int SEL>   // 0: g_A1m -> g_C0x ; 1: g_A2m -> g_C01
__global__ void c0_kernel() {
    int m = blockIdx.x * 256 + threadIdx.x;          // 8192 threads
    const uint8_t* base = SEL ? g_A2m : g_A1m;
    int rt = m >> 7, r = m & 127, cnt = 0;
    #pragma unroll
    for (int ks = 0; ks < 4; ks++) {
        const uint4* rowp = (const uint4*)(base + ((size_t)(rt * 4 + ks) * 128 + r) * 128);
        #pragma unroll
        for (int c2 = 0; c2 < 8; c2++) {
            uint4 v = rowp[c2];
            cnt += __popc(v.x) + __popc(v.y) + __popc(v.z) + __popc(v.w);
        }
    }
    if (SEL) g_C01[m] = cnt; else g_C0x[m] = cnt;
}

// w3 [1000,4096] f32 -> bf16 hi|lo B-blocks (nt*128+ks): 256 rows x 128B
__global__ void prep_w3k(const float* __restrict__ w3) {
    size_t t = (size_t)blockIdx.x * 256 + threadIdx.x;   // 1,048,576
    int c  = (int)(t & 7);
    int r  = (int)((t >> 3) & 255);
    int ks = (int)((t >> 11) & 127);
    int nt = (int)(t >> 18);
    int n  = nt * 256 + r;
    int kb = ks * 128 + c * 16;
    bool hi = kb < 8192;
    int ke = (hi ? kb : kb - 8192) >> 1;
    float f[8];
    if (n < 1000) {
        const float4* s = (const float4*)(w3 + (size_t)n * 4096 + ke);
        float4 a = s[0], b = s[1];
        f[0] = a.x; f[1] = a.y; f[2] = a.z; f[3] = a.w;
        f[4] = b.x; f[5] = b.y; f[6] = b.z; f[7] = b.w;
    } else {
        #pragma unroll
        for (int i = 0; i < 8; i++) f[i] = 0.0f;
    }
    uint32_t hwd[8];
    #pragma unroll
    for (int i = 0; i < 8; i++) {
        __nv_bfloat16 h = __float2bfloat16(f[i]);
        if (hi) hwd[i] = (uint32_t)__bfloat16_as_ushort(h);
        else    hwd[i] = (uint32_t)__bfloat16_as_ushort(__float2bfloat16(f[i] - __bfloat162float(h)));
    }
    uint4 o;
    o.x = hwd[0] | (hwd[1] << 16); o.y = hwd[2] | (hwd[3] << 16);
    o.z = hwd[4] | (hwd[5] << 16); o.w = hwd[6] | (hwd[7] << 16);
    *(uint4*)(g_B3 + ((size_t)(nt * 128 + ks) * 256 + r) * 128 + (((c ^ (r & 7)) << 4))) = o;
}

// ============================================================================
// bit-GEMM: CTA 128x128, 8 warps (2m x 4n, warp 64x32), lane tile 8m x 8n.
// K = 4096 bits in 4 k-steps of 1024 bits, 2 smem slots (2 CTAs/SM).
// Accumulators packed 2 cells / u32 (16-bit halves, max 4096 < 2^16).
// LAYER 1: out = {sign,mask} bits of (dot + b1) -> g_A2s/g_A2m
// LAYER 2: out = bf16 sign of (dot + b2)        -> g_A3 (layer-3 A layout)
// ============================================================================
static const int BG_STAGE = 49152;
static const int BG_NST   = 2;
static const int BG_SMEM  = BG_NST * BG_STAGE + 64;     // 98368

template <int LAYER>
__global__ void __launch_bounds__(256, 2) bitgemm(const float* __restrict__ bias) {
    extern __shared__ __align__(128) uint8_t smem[];
    const int tid = threadIdx.x, lane = tid & 31;
    const int wid = tid >> 5;
    const int g = lane >> 2, c = lane & 3;
    const int mt = blockIdx.x, nt = blockIdx.y;
    const int warp_m = (wid >> 2) * 64, warp_n = (wid & 3) * 32;
    const uint32_t sb = smem_u32(smem);
    const uint32_t mbar = sb + BG_NST * BG_STAGE;

    const uint8_t* As = (LAYER == 1) ? g_A1s : g_A2s;
    const uint8_t* Am = (LAYER == 1) ? g_A1m : g_A2m;
    const uint8_t* Bs = (LAYER == 1) ? g_W1b : g_W2b;
    const int*     C0 = (LAYER == 1) ? g_C0x : g_C01;

    if (tid == 0) {
        #pragma unroll
        for (int s = 0; s < BG_NST; s++) MBAR_INIT(mbar + 8 * s, 1);
    }
    __syncthreads();

    auto issue = [&](int ks) {
        const int sl = ks & 1;
        const uint32_t mb = mbar + 8 * sl;
        MBAR_EXPECT_TX(mb, BG_STAGE);
        BULK_G2S(sb + sl * BG_STAGE,         As + (size_t)(mt * 4 + ks) * 16384, 16384, mb);
        BULK_G2S(sb + sl * BG_STAGE + 16384, Am + (size_t)(mt * 4 + ks) * 16384, 16384, mb);
        BULK_G2S(sb + sl * BG_STAGE + 32768, Bs + (size_t)(nt * 4 + ks) * 16384, 16384, mb);
    };
    if (tid == 0) { issue(0); issue(1); }

    // Precomputed swizzled row offsets (XOR with kc<<4 gives chunk address:
    // swizzle lives in bits 4..6, row*128 in bits >=7 — disjoint).
    uint32_t aoff[8], boff[8];
    #pragma unroll
    for (int mi = 0; mi < 8; mi++) {
        uint32_t ar = (uint32_t)(warp_m + g * 8 + mi);
        aoff[mi] = ar * 128 + (((ar >> 3) & 7) << 4);
    }
    #pragma unroll
    for (int nj = 0; nj < 8; nj++) {
        uint32_t br = (uint32_t)(warp_n + c * 8 + nj);
        boff[nj] = br * 128 + (((br >> 3) & 7) << 4);
    }

    uint32_t acc[8][4];   // [mi][pair]: cells (2p) low16, (2p+1) high16
    #pragma unroll
    for (int i = 0; i < 8; i++)
        #pragma unroll
        for (int p = 0; p < 4; p++) acc[i][p] = 0u;

    #pragma unroll 1
    for (int ks = 0; ks < 4; ks++) {
        const int sl = ks & 1;
        MBAR_WAIT(mbar + 8 * sl, (ks >> 1) & 1);
        const uint32_t sA  = sb + sl * BG_STAGE;
        const uint32_t sM  = sA + 16384;
        const uint32_t sBs = sA + 32768;
        #pragma unroll
        for (int kc = 0; kc < 8; kc++) {
            const uint32_t kx = (uint32_t)kc << 4;
            uint4 bv[8];
            #pragma unroll
            for (int nj = 0; nj < 8; nj++) bv[nj] = lds128(sBs + (boff[nj] ^ kx));
            #pragma unroll
            for (int mi = 0; mi < 8; mi++) {
                const uint32_t ax = aoff[mi] ^ kx;
                uint4 av = lds128(sA + ax);
                uint4 mv = lds128(sM + ax);
                #pragma unroll
                for (int p = 0; p < 4; p++) {
                    uint32_t pa = __popc((av.x ^ bv[2*p].x) & mv.x)
                                + __popc((av.y ^ bv[2*p].y) & mv.y)
                                + __popc((av.z ^ bv[2*p].z) & mv.z)
                                + __popc((av.w ^ bv[2*p].w) & mv.w);
                    uint32_t pb = __popc((av.x ^ bv[2*p+1].x) & mv.x)
                                + __popc((av.y ^ bv[2*p+1].y) & mv.y)
                                + __popc((av.z ^ bv[2*p+1].z) & mv.z)
                                + __popc((av.w ^ bv[2*p+1].w) & mv.w);
                    acc[mi][p] += pa + (pb << 16);
                }
            }
        }
        __syncthreads();                    // all warps done with this slot
        if (ks + BG_NST < 4 && tid == 0) issue(ks + BG_NST);
    }

    // ---------------- epilogue ----------------
    float bn[8];
    #pragma unroll
    for (int nj = 0; nj < 8; nj++) bn[nj] = bias[nt * 128 + warp_n + c * 8 + nj];

    #pragma unroll
    for (int mi = 0; mi < 8; mi++) {
        const int rl = warp_m + g * 8 + mi;
        const int m  = mt * 128 + rl;
        const int c0 = C0[m];
        float v[8];
        #pragma unroll
        for (int p = 0; p < 4; p++) {
            int lo = (int)(acc[mi][p] & 0xFFFFu);
            int hi = (int)(acc[mi][p] >> 16);
            v[2*p]     = (float)(c0 - 2 * lo) + bn[2*p];
            v[2*p + 1] = (float)(c0 - 2 * hi) + bn[2*p + 1];
        }

        if (LAYER == 1) {
            uint32_t bs_ = 0, bm_ = 0;
            #pragma unroll
            for (int nj = 0; nj < 8; nj++) {
                uint32_t u = __float_as_uint(v[nj]);
                bs_ |= (u >> 31) << nj;
                bm_ |= (uint32_t)((u << 1) != 0) << nj;
            }
            uint32_t ws = bs_ << (8 * c), wm = bm_ << (8 * c);
            ws |= __shfl_xor_sync(0xFFFFFFFFu, ws, 1);
            ws |= __shfl_xor_sync(0xFFFFFFFFu, ws, 2);
            wm |= __shfl_xor_sync(0xFFFFFFFFu, wm, 1);
            wm |= __shfl_xor_sync(0xFFFFFFFFu, wm, 2);
            if (c == 0) {
                int nw = nt * 4 + (warp_n >> 5);        // global 32-bit word index
                int ks2 = nw >> 5, wi = nw & 31;
                size_t off = ((size_t)(mt * 4 + ks2) * 128 + rl) * 128
                           + (((wi >> 2) ^ ((rl >> 3) & 7)) << 4) + (wi & 3) * 4;
                *(uint32_t*)(g_A2s + off) = ws;
                *(uint32_t*)(g_A2m + off) = wm;
            }
        } else {
            uint32_t pk[4];
            #pragma unroll
            for (int q = 0; q < 4; q++)
                pk[q] = bf16sgn(v[2 * q]) | (bf16sgn(v[2 * q + 1]) << 16);
            const int n0 = nt * 128 + warp_n + c * 8;
            const int nb = n0 * 2;                       // byte offset in 8192B row
            size_t off = ((size_t)(mt * 64 + (nb >> 7)) * 128 + rl) * 128
                       + ((((uint32_t)(nb >> 4) & 7) ^ ((uint32_t)rl & 7)) << 4);
            *(uint4*)(g_A3 + off) = make_uint4(pk[0], pk[1], pk[2], pk[3]);
        }
    }
}

// ============================================================================
// Layer-3 bf16 GEMM: CTA 128x256, K=8192 (hi|lo), 4-stage bulk pipeline
// ============================================================================
static const int G3_STAGE = 49152;
static const int G3_SMEM  = 4 * G3_STAGE + 64 + 1024;

__global__ void __launch_bounds__(256, 1) gemm3(const float* __restrict__ bias,
                                                float* __restrict__ outf) {
    extern __shared__ __align__(128) uint8_t smem[];
    const int tid = threadIdx.x, lane = tid & 31, wid = tid >> 5;
    const int mt = blockIdx.x, nt = blockIdx.y;
    const int m_w = (wid >> 2) * 64, n_w = (wid & 3) * 64;
    const uint32_t sbase = smem_u32(smem);
    const uint32_t mbar  = sbase + 4 * G3_STAGE;
    float* s_bias = (float*)(smem + 4 * G3_STAGE + 64);

    const uint8_t* Ablk = g_A3 + (size_t)mt * 64 * 16384;
    const uint8_t* Bblk = g_B3 + (size_t)nt * 128 * 32768;

    if (tid == 0) {
        #pragma unroll
        for (int s = 0; s < 4; s++) MBAR_INIT(mbar + 8 * s, 1);
    }
    {
        int n = nt * 256 + tid;
        s_bias[tid] = (n < 1000) ? bias[n] : 0.0f;
    }
    __syncthreads();

    auto issue = [&](int ks) {
        if (tid == 0) {
            const int sl = ks & 3;
            const uint32_t mb = mbar + 8 * sl;
            MBAR_EXPECT_TX(mb, G3_STAGE);
            BULK_G2S(sbase + sl * G3_STAGE,         Ablk + (size_t)(ks & 63) * 16384, 16384, mb);
            BULK_G2S(sbase + sl * G3_STAGE + 16384, Bblk + (size_t)ks * 32768,        32768, mb);
        }
    };

    float cf[4][8][4];
    #pragma unroll
    for (int a = 0; a < 4; a++)
        #pragma unroll
        for (int b = 0; b < 8; b++)
            #pragma unroll
            for (int q = 0; q < 4; q++) cf[a][b][q] = 0.0f;

    #pragma unroll
    for (int s = 0; s < 4; s++) issue(s);

    const uint32_t a_row = (uint32_t)(m_w + ((lane >> 3) & 1) * 8 + (lane & 7));
    const uint32_t a_chi = (uint32_t)(lane >> 4);
    const uint32_t b_row = (uint32_t)(n_w + (lane & 7));
    const uint32_t b_chi = (uint32_t)((lane >> 3) & 1);

    #pragma unroll 1
    for (int ks = 0; ks < 128; ks++) {
        const int sl = ks & 3;
        MBAR_WAIT(mbar + 8 * sl, (ks >> 2) & 1);
        const uint32_t sA = sbase + sl * G3_STAGE;
        const uint32_t sB = sA + 16384;

        #pragma unroll
        for (int kst = 0; kst < 4; kst++) {
            uint32_t a[4][4];
            #pragma unroll
            for (int mi = 0; mi < 4; mi++) {
                uint32_t rl = a_row + mi * 16;
                uint32_t cc = (uint32_t)(kst * 2) + a_chi;
                LDSM_X4(a[mi], sA + rl * 128 + (((cc ^ (rl & 7)) << 4)));
            }
            uint32_t b[8][2];
            #pragma unroll
            for (int ni = 0; ni < 8; ni++) {
                uint32_t rl = b_row + ni * 8;
                uint32_t cc = (uint32_t)(kst * 2) + b_chi;
                LDSM_X2(b[ni], sB + rl * 128 + (((cc ^ (rl & 7)) << 4)));
            }
            #pragma unroll
            for (int mi = 0; mi < 4; mi++)
                #pragma unroll
                for (int ni = 0; ni < 8; ni++)
                    mma_bf16(cf[mi][ni], a[mi], b[ni][0], b[ni][1]);
        }
        __syncthreads();
        if (ks + 4 < 128) issue(ks + 4);
    }

    const int g = lane >> 2, t4 = lane & 3;
    #pragma unroll
    for (int mi = 0; mi < 4; mi++) {
        const int rl0 = m_w + mi * 16 + g;
        #pragma unroll
        for (int ni = 0; ni < 8; ni++) {
            const int nl = n_w + ni * 8 + t4 * 2;
            const int ng = nt * 256 + nl;
            const size_t r0 = (size_t)(mt * 128 + rl0);
            float f0 = cf[mi][ni][0] + s_bias[nl];
            float f1 = cf[mi][ni][1] + s_bias[nl + 1];
            float f2 = cf[mi][ni][2] + s_bias[nl];
            float f3 = cf[mi][ni][3] + s_bias[nl + 1];
            if (ng < 1000) {
                outf[r0 * 1000 + ng]       = f0;
                outf[(r0 + 8) * 1000 + ng] = f2;
            }
            if (ng + 1 < 1000) {
                outf[r0 * 1000 + ng + 1]       = f1;
                outf[(r0 + 8) * 1000 + ng + 1] = f3;
            }
        }
    }
}

// ============================================================================
// kernel_launch — launch index 3 (the profiled one) = bitgemm<1>
// ============================================================================
extern "C" void kernel_launch(void* const* d_in, const int* in_sizes, int n_in,
                              void* d_out, int out_size) {
    (void)in_sizes; (void)n_in; (void)out_size;
    const float* x  = (const float*)d_in[0];
    const float* w1 = (const float*)d_in[1];
    const float* b1 = (const float*)d_in[2];
    const float* w2 = (const float*)d_in[3];
    const float* b2 = (const float*)d_in[4];
    const float* w3 = (const float*)d_in[5];
    const float* b3 = (const float*)d_in[6];
    float* out = (float*)d_out;

    cudaFuncSetAttribute(bitgemm<1>, cudaFuncAttributeMaxDynamicSharedMemorySize, BG_SMEM);
    cudaFuncSetAttribute(bitgemm<2>, cudaFuncAttributeMaxDynamicSharedMemorySize, BG_SMEM);
    cudaFuncSetAttribute(gemm3,      cudaFuncAttributeMaxDynamicSharedMemorySize, G3_SMEM);

    pack_bits<0><<<4096, 256>>>(x);                       // 0
    pack_bits<1><<<2048, 256>>>(w1);                      // 1
    c0_kernel<0><<<32, 256>>>();                          // 2
    bitgemm<1><<<dim3(64, 32), 256, BG_SMEM>>>(b1);       // 3  <- profiled
    pack_bits<2><<<2048, 256>>>(w2);                      // 4
    c0_kernel<1><<<32, 256>>>();                          // 5
    bitgemm<2><<<dim3(64, 32), 256, BG_SMEM>>>(b2);       // 6
    prep_w3k<<<4096, 256>>>(w3);                          // 7
    gemm3<<<dim3(64, 4), 256, G3_SMEM>>>(b3, out);        // 8
}